// round 15
// baseline (speedup 1.0000x reference)
#include <cuda_runtime.h>
#include <math.h>

#define SR    16000
#define WIN   400
#define HOP   160
#define NFFT  512
#define NBIN  257
#define NMELS 40
#define NMFCC 13
#define BATCH 64
#define LEN   160000
#define NF    998
#define OUTC  39
#define NPAIR (BATCH * NF / 2)   // 31936 packed FFTs
#define GROUPS 4                 // FFT groups (64 thr each) per CTA
#define THREADS (GROUPS * 64)
#define NDCT  16                 // only mfcc[0..14] are ever needed
#define MAGSTRIDE 264            // compact magnitude layout stride (floats)
#define NTASK 80                 // 2 frames x 40 mel filters

#ifndef M_PI
#define M_PI 3.14159265358979323846
#endif

// ---------------- constant tables (built by cheap init kernel each launch) ----------------
__device__ float d_window[WIN];
__device__ float d_fbw[NMELS * 33];   // packed sparse mel weights, stride 33 (zero-padded)
__device__ int   d_klo[NMELS];
__device__ int   d_flen[NMELS];
__device__ float d_dct16[NDCT * 41];  // first 16 DCT rows, stride 41 (zero-padded col 40)
__device__ int   d_tmap[NTASK];       // load-balanced mel task permutation

__global__ void init_consts_kernel() {
    const int g  = blockIdx.x * blockDim.x + threadIdx.x;
    const int ng = gridDim.x * blockDim.x;
    const int t  = threadIdx.x;

    __shared__ double bins[NMELS + 2];
    if (t < NMELS + 2) {
        double high_mel = 2595.0 * log10(1.0 + (SR / 2.0) / 700.0);
        double mel = high_mel * ((double)t / (double)(NMELS + 1));
        double hz = 700.0 * (exp(mel * (2.302585092994045684 / 2595.0)) - 1.0);  // 10^x = e^{x ln10}
        bins[t] = floor((double)(NFFT + 1) * hz / (double)SR);
    }
    __syncthreads();

    for (int n = g; n < WIN; n += ng)
        d_window[n] = 0.54f - 0.46f * cosf((float)(2.0 * M_PI / (double)WIN) * (float)n);

    for (int i = g; i < NMELS * 33; i += ng) {
        int r = i / 33, j = i - r * 33;
        int lo = (int)bins[r], c = (int)bins[r + 1], hi = (int)bins[r + 2];
        int k = lo + j;
        float w = 0.0f;
        if (k < c)       w = (float)(k - lo) / (float)(c - lo);
        else if (k < hi) w = (float)(hi - k) / (float)(hi - c);
        d_fbw[i] = w;
    }
    if (g < NMELS) {
        int lo = (int)bins[g], hi = (int)bins[g + 2];
        d_klo[g] = lo;
        int len = hi - lo;
        d_flen[g] = len > 33 ? 33 : len;      // max actual width is 31
    }
    for (int i = g; i < NDCT * 41; i += ng) {
        int k = i / 41, n = i - k * 41;
        float val = 0.0f;
        if (n < NMELS) {
            float arg = (float)(M_PI / 80.0) * (float)(k * (2 * n + 1));
            float sc = (k == 0) ? 0.158113883008419f : 0.223606797749979f; // sqrt(1/40), sqrt(2/40)
            val = sc * cosf(arg);
        }
        d_dct16[i] = val;
    }

    // load-balanced mel task permutation: sort tasks by filter length desc,
    // longest 32 -> slots 32..63 (warp1), next 32 -> slots 0..31 (warp0),
    // shortest 16 -> slots 64..79 (warp0 second pass).
    if (blockIdx.x == 0 && t == 0) {
        int lens[NTASK], idx[NTASK];
        for (int i = 0; i < NTASK; i++) {
            int m = i % NMELS;
            int lo = (int)bins[m], hi = (int)bins[m + 2];
            int L = hi - lo; if (L > 33) L = 33;
            lens[i] = L; idx[i] = i;
        }
        for (int a = 0; a < NTASK; a++) {           // selection sort desc
            int best = a;
            for (int c = a + 1; c < NTASK; c++) if (lens[c] > lens[best]) best = c;
            int tl = lens[a]; lens[a] = lens[best]; lens[best] = tl;
            int ti = idx[a];  idx[a]  = idx[best];  idx[best]  = ti;
        }
        for (int a = 0; a < NTASK; a++) {
            int slot = (a < 32) ? (32 + a) : ((a < 64) ? (a - 32) : a);
            d_tmap[slot] = idx[a];
        }
    }
}

// ---------------- complex helpers ----------------
__device__ __forceinline__ float2 cadd(float2 a, float2 b) { return make_float2(a.x + b.x, a.y + b.y); }
__device__ __forceinline__ float2 csub(float2 a, float2 b) { return make_float2(a.x - b.x, a.y - b.y); }
__device__ __forceinline__ float2 cmul(float2 a, float2 b) {
    return make_float2(a.x * b.x - a.y * b.y, a.x * b.y + a.y * b.x);
}
__device__ __forceinline__ float2 negi(float2 a) { return make_float2(a.y, -a.x); }  // -i*a

__device__ __forceinline__ void dft8(float2 v[8]) {
    const float c = 0.70710678118654752f;
    float2 t0 = cadd(v[0], v[4]), t1 = csub(v[0], v[4]);
    float2 t2 = cadd(v[2], v[6]), t3 = csub(v[2], v[6]);
    float2 E0 = cadd(t0, t2), E2 = csub(t0, t2);
    float2 t3n = negi(t3);
    float2 E1 = cadd(t1, t3n), E3 = csub(t1, t3n);
    float2 u0 = cadd(v[1], v[5]), u1 = csub(v[1], v[5]);
    float2 u2 = cadd(v[3], v[7]), u3 = csub(v[3], v[7]);
    float2 O0 = cadd(u0, u2), O2 = csub(u0, u2);
    float2 u3n = negi(u3);
    float2 O1 = cadd(u1, u3n), O3 = csub(u1, u3n);
    O1 = make_float2(c * (O1.x + O1.y), c * (O1.y - O1.x));
    O2 = negi(O2);
    O3 = make_float2(c * (O3.y - O3.x), -c * (O3.x + O3.y));
    v[0] = cadd(E0, O0); v[4] = csub(E0, O0);
    v[1] = cadd(E1, O1); v[5] = csub(E1, O1);
    v[2] = cadd(E2, O2); v[6] = csub(E2, O2);
    v[3] = cadd(E3, O3); v[7] = csub(E3, O3);
}

// apply twiddle powers w^1..w^7 with log-depth chain (depth 3 instead of 7)
__device__ __forceinline__ void twiddle_powers(float2 v[8], float2 w1) {
    float2 w2 = cmul(w1, w1);
    float2 w3 = cmul(w2, w1);
    float2 w4 = cmul(w2, w2);
    v[1] = cmul(v[1], w1);
    v[2] = cmul(v[2], w2);
    v[3] = cmul(v[3], w3);
    v[4] = cmul(v[4], w4);
    v[5] = cmul(v[5], cmul(w4, w1));
    v[6] = cmul(v[6], cmul(w4, w2));
    v[7] = cmul(v[7], cmul(w4, w3));
}

// ---------------- main kernel: one frame-pair per 64-thread group, 4 groups/CTA ----------------
__global__ __launch_bounds__(THREADS, 5) void mfcc_kernel(const float* __restrict__ x,
                                                          float* __restrict__ out) {
    __shared__ float2 sZ[GROUPS][568];            // FFT exchange buffer; mag overlay
    __shared__ float  sMel[GROUPS][2][NMELS];
    __shared__ float  sMfcc[GROUPS][2][NDCT];
    __shared__ float  sD1[GROUPS][2][NDCT];
    __shared__ float  sFbw[NMELS * 33];
    __shared__ int    sKlo[NMELS];
    __shared__ int    sLen[NMELS];
    __shared__ float  sDct[NDCT * 41];
    __shared__ int    sTask[NTASK];

    const int tid = threadIdx.x;
    const int lt  = tid & 63;
    const int grp = tid >> 6;
    const int p   = blockIdx.x * GROUPS + grp;    // packed-pair id (grid exact)
    const int b   = p / (NF / 2);
    const int fp  = p - b * (NF / 2);
    const int f0  = 2 * fp;
    const size_t row = (size_t)b * LEN;
    const int base0 = f0 * HOP;

    // cooperative table staging (coalesced), CTA-wide — amortized over 4 groups
    for (int i = tid; i < NMELS * 33; i += THREADS) sFbw[i] = d_fbw[i];
    for (int i = tid; i < NDCT * 41;  i += THREADS) sDct[i] = d_dct16[i];
    if (tid < NMELS) { sKlo[tid] = d_klo[tid]; sLen[tid] = d_flen[tid]; }
    if (tid < NTASK) sTask[tid] = d_tmap[tid];

    float2 v[8];

    // ---- load + pre-emphasis + window (direct dual LDG; coalesced & line-shared) ----
    #pragma unroll
    for (int j = 0; j < 8; j++) {
        int n = lt + 64 * j;
        if (n < WIN) {
            float w = d_window[n];
            int i0 = base0 + n;
            float a0 = x[row + i0];
            float p0 = (i0 == 0) ? a0 : (a0 - 0.97f * x[row + i0 - 1]);
            int i1 = i0 + HOP;
            float a1 = x[row + i1];
            float p1 = a1 - 0.97f * x[row + i1 - 1];
            v[j] = make_float2(p0 * w, p1 * w);
        } else {
            v[j] = make_float2(0.0f, 0.0f);
        }
    }
    __syncthreads();   // tables staged + sZ free

    // ---- stage 1: radix-8 over stride 64, twiddle W512^(t*s) ----
    dft8(v);
    {
        float sv, cv;
        __sincosf(-0.01227184630308513f * (float)lt, &sv, &cv);   // -2*pi/512 * lt
        twiddle_powers(v, make_float2(cv, sv));
    }

    // exchange 1: store z_s[t] at 72*s + t ; read z_s[n'' + 8j']
    #pragma unroll
    for (int s = 0; s < 8; s++) sZ[grp][72 * s + lt] = v[s];
    __syncthreads();
    {
        const int s = lt >> 3, npp = lt & 7;
        #pragma unroll
        for (int j = 0; j < 8; j++) v[j] = sZ[grp][72 * s + npp + 8 * j];
        __syncthreads();

        // ---- stage 2: radix-8, twiddle W64^(n''*s') ----
        dft8(v);
        {
            float sv, cv;
            __sincosf(-0.0981747704246810f * (float)npp, &sv, &cv); // -2*pi/64 * npp
            twiddle_powers(v, make_float2(cv, sv));
        }

        // exchange 2: store at 68*n'' + 8*s' + s (bank-bijective per half-warp)
        #pragma unroll
        for (int sp = 0; sp < 8; sp++) sZ[grp][68 * npp + 8 * sp + s] = v[sp];
    }
    __syncthreads();
    {
        const int sp = lt >> 3, s = lt & 7;       // outputs X[64m + 8sp + s] = X[64m + lt]
        #pragma unroll
        for (int j = 0; j < 8; j++) v[j] = sZ[grp][68 * j + 8 * sp + s];
        __syncthreads();

        // ---- stage 3: radix-8 -> store X flat at slot 64*m + lt ----
        dft8(v);
        #pragma unroll
        for (int m = 0; m < 8; m++) sZ[grp][64 * m + lt] = v[m];
    }
    __syncthreads();

    // ---- conjugate-symmetry unpack into registers, then compact stride-1 store ----
    float m0[4], m1[4];
    #pragma unroll
    for (int j = 0; j < 4; j++) {
        int k  = lt + 64 * j;                     // 0..255
        int kk = (NFFT - k) & (NFFT - 1);
        float2 u = sZ[grp][k];
        float2 w = sZ[grp][kk];
        float Ar = 0.5f * (u.x + w.x), Ai = 0.5f * (u.y - w.y);
        float Br = 0.5f * (u.y + w.y), Bi = 0.5f * (w.x - u.x);
        m0[j] = sqrtf(Ar * Ar + Ai * Ai);
        m1[j] = sqrtf(Br * Br + Bi * Bi);
    }
    float e0 = 0.0f, e1 = 0.0f;
    if (lt == 0) {                                // k = 256 (Nyquist)
        float2 u = sZ[grp][256];
        e0 = fabsf(u.x); e1 = fabsf(u.y);
    }
    __syncthreads();                              // all spectrum reads done
    float* __restrict__ sMagF = (float*)sZ[grp];  // overlay: mag0 at [k], mag1 at [264+k]
    #pragma unroll
    for (int j = 0; j < 4; j++) {
        int k = lt + 64 * j;
        sMagF[k] = m0[j];
        sMagF[MAGSTRIDE + k] = m1[j];
    }
    if (lt == 0) { sMagF[256] = e0; sMagF[MAGSTRIDE + 256] = e1; }
    __syncthreads();

    // ---- mel filterbank + log: load-balanced task permutation ----
    #pragma unroll
    for (int sidx = lt; sidx < NTASK; sidx += 64) {
        int task = sTask[sidx];
        int fr = task / NMELS, m = task - fr * NMELS;
        const int klo = sKlo[m], len = sLen[m];
        const float* __restrict__ fw = sFbw + m * 33;
        const float* __restrict__ mg = sMagF + fr * MAGSTRIDE + klo;
        float acc = 0.0f;
        for (int j = 0; j < len; j++) acc = fmaf(fw[j], mg[j], acc);
        sMel[grp][fr][m] = __logf(acc + 1e-20f);
    }
    __syncthreads();

    // ---- DCT-II ortho, 16 rows, split dot across thread pairs ----
    {
        int task = lt >> 1;                       // 0..31 = (fr, m)
        int half = lt & 1;
        int fr = task >> 4, m = task & 15;
        const float* __restrict__ dr = sDct + m * 41 + half * 20;
        const float* __restrict__ ml = sMel[grp][fr] + half * 20;
        float acc = 0.0f;
        #pragma unroll
        for (int n = 0; n < 20; n++) acc = fmaf(dr[n], ml[n], acc);
        acc += __shfl_xor_sync(0xffffffffu, acc, 1);
        if (half == 0) sMfcc[grp][fr][m] = acc;
    }
    __syncthreads();

    // ---- first delta over coefficients (valid for c<=14; we need c<=13) ----
    if (lt < 32) {
        int fr = lt >> 4, c = lt & 15;
        float val = 0.0f;
        if (c >= 1 && c <= 14) val = 0.5f * (sMfcc[grp][fr][c + 1] - sMfcc[grp][fr][c - 1]);
        sD1[grp][fr][c] = val;
    }
    __syncthreads();

    // ---- write [mfcc[0:13], d1[0:13], d2[0:13]] for both frames ----
    #pragma unroll
    for (int i = lt; i < 2 * OUTC; i += 64) {
        int fr = i / OUTC, c = i - fr * OUTC;
        int frame = b * NF + f0 + fr;
        float val;
        if (c < NMFCC) {
            val = sMfcc[grp][fr][c];
        } else if (c < 2 * NMFCC) {
            val = sD1[grp][fr][c - NMFCC];
        } else {
            int cc = c - 2 * NMFCC;
            val = (cc >= 1) ? 0.5f * (sD1[grp][fr][cc + 1] - sD1[grp][fr][cc - 1]) : 0.0f;
        }
        out[(size_t)frame * OUTC + c] = val;
    }
}

extern "C" void kernel_launch(void* const* d_in, const int* in_sizes, int n_in,
                              void* d_out, int out_size) {
    (void)in_sizes; (void)n_in; (void)out_size;
    const float* x = (const float*)d_in[0];
    float* out = (float*)d_out;
    init_consts_kernel<<<8, 128>>>();
    mfcc_kernel<<<NPAIR / GROUPS, THREADS>>>(x, out);
}

// round 16
// speedup vs baseline: 1.9726x; 1.9726x over previous
#include <cuda_runtime.h>
#include <math.h>

#define SR    16000
#define WIN   400
#define HOP   160
#define NFFT  512
#define NBIN  257
#define NMELS 40
#define NMFCC 13
#define BATCH 64
#define LEN   160000
#define NF    998
#define OUTC  39
#define NPAIR (BATCH * NF / 2)   // 31936 packed FFTs
#define GROUPS 4                 // FFT groups (64 thr each) per CTA
#define THREADS (GROUPS * 64)
#define NDCT  16                 // only mfcc[0..14] are ever needed
#define MAGSTRIDE 264            // compact magnitude layout stride (floats)
#define NTASK 80                 // 2 frames x 40 mel filters

#ifndef M_PI
#define M_PI 3.14159265358979323846
#endif

// ---------------- constant tables (built by cheap init kernel each launch) ----------------
__device__ float d_window[WIN];
__device__ float d_fbw[NMELS * 33];   // packed sparse mel weights, stride 33 (zero-padded)
__device__ int   d_klo[NMELS];
__device__ int   d_flen[NMELS];
__device__ float d_dct16[NDCT * 41];  // first 16 DCT rows, stride 41 (zero-padded col 40)
__device__ int   d_tmap[NTASK];       // load-balanced mel task permutation

__global__ void init_consts_kernel() {
    const int g  = blockIdx.x * blockDim.x + threadIdx.x;
    const int ng = gridDim.x * blockDim.x;
    const int t  = threadIdx.x;

    __shared__ double bins[NMELS + 2];
    if (t < NMELS + 2) {
        double high_mel = 2595.0 * log10(1.0 + (SR / 2.0) / 700.0);
        double mel = high_mel * ((double)t / (double)(NMELS + 1));
        double hz = 700.0 * (exp(mel * (2.302585092994045684 / 2595.0)) - 1.0);  // 10^x = e^{x ln10}
        bins[t] = floor((double)(NFFT + 1) * hz / (double)SR);
    }
    __syncthreads();

    for (int n = g; n < WIN; n += ng)
        d_window[n] = 0.54f - 0.46f * cosf((float)(2.0 * M_PI / (double)WIN) * (float)n);

    for (int i = g; i < NMELS * 33; i += ng) {
        int r = i / 33, j = i - r * 33;
        int lo = (int)bins[r], c = (int)bins[r + 1], hi = (int)bins[r + 2];
        int k = lo + j;
        float w = 0.0f;
        if (k < c)       w = (float)(k - lo) / (float)(c - lo);
        else if (k < hi) w = (float)(hi - k) / (float)(hi - c);
        d_fbw[i] = w;
    }
    if (g < NMELS) {
        int lo = (int)bins[g], hi = (int)bins[g + 2];
        d_klo[g] = lo;
        int len = hi - lo;
        d_flen[g] = len > 33 ? 33 : len;      // max actual width is 31
    }
    for (int i = g; i < NDCT * 41; i += ng) {
        int k = i / 41, n = i - k * 41;
        float val = 0.0f;
        if (n < NMELS) {
            float arg = (float)(M_PI / 80.0) * (float)(k * (2 * n + 1));
            float sc = (k == 0) ? 0.158113883008419f : 0.223606797749979f; // sqrt(1/40), sqrt(2/40)
            val = sc * cosf(arg);
        }
        d_dct16[i] = val;
    }

    // Load-balanced mel task permutation — ANALYTIC, fully parallel.
    // Mel filter widths are monotone non-decreasing in m, so "sorted by length
    // descending" == "descending m" (fr=0/1 tie). a-th longest task:
    //   m = 39 - (a>>1), fr = a&1.
    // Slot layout: longest 32 -> slots 32..63 (warp1), next 32 -> slots 0..31
    // (warp0 pass 1), shortest 16 -> slots 64..79 (warp0 pass 2).
    if (g < NTASK) {
        int a = g;
        int m  = (NMELS - 1) - (a >> 1);
        int fr = a & 1;
        int slot = (a < 32) ? (32 + a) : ((a < 64) ? (a - 32) : a);
        d_tmap[slot] = fr * NMELS + m;
    }
}

// ---------------- complex helpers ----------------
__device__ __forceinline__ float2 cadd(float2 a, float2 b) { return make_float2(a.x + b.x, a.y + b.y); }
__device__ __forceinline__ float2 csub(float2 a, float2 b) { return make_float2(a.x - b.x, a.y - b.y); }
__device__ __forceinline__ float2 cmul(float2 a, float2 b) {
    return make_float2(a.x * b.x - a.y * b.y, a.x * b.y + a.y * b.x);
}
__device__ __forceinline__ float2 negi(float2 a) { return make_float2(a.y, -a.x); }  // -i*a

__device__ __forceinline__ void dft8(float2 v[8]) {
    const float c = 0.70710678118654752f;
    float2 t0 = cadd(v[0], v[4]), t1 = csub(v[0], v[4]);
    float2 t2 = cadd(v[2], v[6]), t3 = csub(v[2], v[6]);
    float2 E0 = cadd(t0, t2), E2 = csub(t0, t2);
    float2 t3n = negi(t3);
    float2 E1 = cadd(t1, t3n), E3 = csub(t1, t3n);
    float2 u0 = cadd(v[1], v[5]), u1 = csub(v[1], v[5]);
    float2 u2 = cadd(v[3], v[7]), u3 = csub(v[3], v[7]);
    float2 O0 = cadd(u0, u2), O2 = csub(u0, u2);
    float2 u3n = negi(u3);
    float2 O1 = cadd(u1, u3n), O3 = csub(u1, u3n);
    O1 = make_float2(c * (O1.x + O1.y), c * (O1.y - O1.x));
    O2 = negi(O2);
    O3 = make_float2(c * (O3.y - O3.x), -c * (O3.x + O3.y));
    v[0] = cadd(E0, O0); v[4] = csub(E0, O0);
    v[1] = cadd(E1, O1); v[5] = csub(E1, O1);
    v[2] = cadd(E2, O2); v[6] = csub(E2, O2);
    v[3] = cadd(E3, O3); v[7] = csub(E3, O3);
}

// apply twiddle powers w^1..w^7 with log-depth chain (depth 3 instead of 7)
__device__ __forceinline__ void twiddle_powers(float2 v[8], float2 w1) {
    float2 w2 = cmul(w1, w1);
    float2 w3 = cmul(w2, w1);
    float2 w4 = cmul(w2, w2);
    v[1] = cmul(v[1], w1);
    v[2] = cmul(v[2], w2);
    v[3] = cmul(v[3], w3);
    v[4] = cmul(v[4], w4);
    v[5] = cmul(v[5], cmul(w4, w1));
    v[6] = cmul(v[6], cmul(w4, w2));
    v[7] = cmul(v[7], cmul(w4, w3));
}

// ---------------- main kernel: one frame-pair per 64-thread group, 4 groups/CTA ----------------
__global__ __launch_bounds__(THREADS, 5) void mfcc_kernel(const float* __restrict__ x,
                                                          float* __restrict__ out) {
    __shared__ float2 sZ[GROUPS][568];            // FFT exchange buffer; mag overlay
    __shared__ float  sMel[GROUPS][2][NMELS];
    __shared__ float  sMfcc[GROUPS][2][NDCT];
    __shared__ float  sD1[GROUPS][2][NDCT];
    __shared__ float  sFbw[NMELS * 33];
    __shared__ int    sKlo[NMELS];
    __shared__ int    sLen[NMELS];
    __shared__ float  sDct[NDCT * 41];
    __shared__ int    sTask[NTASK];

    const int tid = threadIdx.x;
    const int lt  = tid & 63;
    const int grp = tid >> 6;
    const int p   = blockIdx.x * GROUPS + grp;    // packed-pair id (grid exact)
    const int b   = p / (NF / 2);
    const int fp  = p - b * (NF / 2);
    const int f0  = 2 * fp;
    const size_t row = (size_t)b * LEN;
    const int base0 = f0 * HOP;

    // cooperative table staging (coalesced), CTA-wide — amortized over 4 groups
    for (int i = tid; i < NMELS * 33; i += THREADS) sFbw[i] = d_fbw[i];
    for (int i = tid; i < NDCT * 41;  i += THREADS) sDct[i] = d_dct16[i];
    if (tid < NMELS) { sKlo[tid] = d_klo[tid]; sLen[tid] = d_flen[tid]; }
    if (tid < NTASK) sTask[tid] = d_tmap[tid];

    float2 v[8];

    // ---- load + pre-emphasis + window (direct dual LDG; coalesced & line-shared) ----
    #pragma unroll
    for (int j = 0; j < 8; j++) {
        int n = lt + 64 * j;
        if (n < WIN) {
            float w = d_window[n];
            int i0 = base0 + n;
            float a0 = x[row + i0];
            float p0 = (i0 == 0) ? a0 : (a0 - 0.97f * x[row + i0 - 1]);
            int i1 = i0 + HOP;
            float a1 = x[row + i1];
            float p1 = a1 - 0.97f * x[row + i1 - 1];
            v[j] = make_float2(p0 * w, p1 * w);
        } else {
            v[j] = make_float2(0.0f, 0.0f);
        }
    }
    __syncthreads();   // tables staged + sZ free

    // ---- stage 1: radix-8 over stride 64, twiddle W512^(t*s) ----
    dft8(v);
    {
        float sv, cv;
        __sincosf(-0.01227184630308513f * (float)lt, &sv, &cv);   // -2*pi/512 * lt
        twiddle_powers(v, make_float2(cv, sv));
    }

    // exchange 1: store z_s[t] at 72*s + t ; read z_s[n'' + 8j']
    #pragma unroll
    for (int s = 0; s < 8; s++) sZ[grp][72 * s + lt] = v[s];
    __syncthreads();
    {
        const int s = lt >> 3, npp = lt & 7;
        #pragma unroll
        for (int j = 0; j < 8; j++) v[j] = sZ[grp][72 * s + npp + 8 * j];
        __syncthreads();

        // ---- stage 2: radix-8, twiddle W64^(n''*s') ----
        dft8(v);
        {
            float sv, cv;
            __sincosf(-0.0981747704246810f * (float)npp, &sv, &cv); // -2*pi/64 * npp
            twiddle_powers(v, make_float2(cv, sv));
        }

        // exchange 2: store at 68*n'' + 8*s' + s (bank-bijective per half-warp)
        #pragma unroll
        for (int sp = 0; sp < 8; sp++) sZ[grp][68 * npp + 8 * sp + s] = v[sp];
    }
    __syncthreads();
    {
        const int sp = lt >> 3, s = lt & 7;       // outputs X[64m + 8sp + s] = X[64m + lt]
        #pragma unroll
        for (int j = 0; j < 8; j++) v[j] = sZ[grp][68 * j + 8 * sp + s];
        __syncthreads();

        // ---- stage 3: radix-8 -> store X flat at slot 64*m + lt ----
        dft8(v);
        #pragma unroll
        for (int m = 0; m < 8; m++) sZ[grp][64 * m + lt] = v[m];
    }
    __syncthreads();

    // ---- conjugate-symmetry unpack into registers, then compact stride-1 store ----
    float m0[4], m1[4];
    #pragma unroll
    for (int j = 0; j < 4; j++) {
        int k  = lt + 64 * j;                     // 0..255
        int kk = (NFFT - k) & (NFFT - 1);
        float2 u = sZ[grp][k];
        float2 w = sZ[grp][kk];
        float Ar = 0.5f * (u.x + w.x), Ai = 0.5f * (u.y - w.y);
        float Br = 0.5f * (u.y + w.y), Bi = 0.5f * (w.x - u.x);
        m0[j] = sqrtf(Ar * Ar + Ai * Ai);
        m1[j] = sqrtf(Br * Br + Bi * Bi);
    }
    float e0 = 0.0f, e1 = 0.0f;
    if (lt == 0) {                                // k = 256 (Nyquist)
        float2 u = sZ[grp][256];
        e0 = fabsf(u.x); e1 = fabsf(u.y);
    }
    __syncthreads();                              // all spectrum reads done
    float* __restrict__ sMagF = (float*)sZ[grp];  // overlay: mag0 at [k], mag1 at [264+k]
    #pragma unroll
    for (int j = 0; j < 4; j++) {
        int k = lt + 64 * j;
        sMagF[k] = m0[j];
        sMagF[MAGSTRIDE + k] = m1[j];
    }
    if (lt == 0) { sMagF[256] = e0; sMagF[MAGSTRIDE + 256] = e1; }
    __syncthreads();

    // ---- mel filterbank + log: load-balanced task permutation ----
    #pragma unroll
    for (int sidx = lt; sidx < NTASK; sidx += 64) {
        int task = sTask[sidx];
        int fr = task / NMELS, m = task - fr * NMELS;
        const int klo = sKlo[m], len = sLen[m];
        const float* __restrict__ fw = sFbw + m * 33;
        const float* __restrict__ mg = sMagF + fr * MAGSTRIDE + klo;
        float acc = 0.0f;
        for (int j = 0; j < len; j++) acc = fmaf(fw[j], mg[j], acc);
        sMel[grp][fr][m] = __logf(acc + 1e-20f);
    }
    __syncthreads();

    // ---- DCT-II ortho, 16 rows, split dot across thread pairs ----
    {
        int task = lt >> 1;                       // 0..31 = (fr, m)
        int half = lt & 1;
        int fr = task >> 4, m = task & 15;
        const float* __restrict__ dr = sDct + m * 41 + half * 20;
        const float* __restrict__ ml = sMel[grp][fr] + half * 20;
        float acc = 0.0f;
        #pragma unroll
        for (int n = 0; n < 20; n++) acc = fmaf(dr[n], ml[n], acc);
        acc += __shfl_xor_sync(0xffffffffu, acc, 1);
        if (half == 0) sMfcc[grp][fr][m] = acc;
    }
    __syncthreads();

    // ---- first delta over coefficients (valid for c<=14; we need c<=13) ----
    if (lt < 32) {
        int fr = lt >> 4, c = lt & 15;
        float val = 0.0f;
        if (c >= 1 && c <= 14) val = 0.5f * (sMfcc[grp][fr][c + 1] - sMfcc[grp][fr][c - 1]);
        sD1[grp][fr][c] = val;
    }
    __syncthreads();

    // ---- write [mfcc[0:13], d1[0:13], d2[0:13]] for both frames ----
    #pragma unroll
    for (int i = lt; i < 2 * OUTC; i += 64) {
        int fr = i / OUTC, c = i - fr * OUTC;
        int frame = b * NF + f0 + fr;
        float val;
        if (c < NMFCC) {
            val = sMfcc[grp][fr][c];
        } else if (c < 2 * NMFCC) {
            val = sD1[grp][fr][c - NMFCC];
        } else {
            int cc = c - 2 * NMFCC;
            val = (cc >= 1) ? 0.5f * (sD1[grp][fr][cc + 1] - sD1[grp][fr][cc - 1]) : 0.0f;
        }
        out[(size_t)frame * OUTC + c] = val;
    }
}

extern "C" void kernel_launch(void* const* d_in, const int* in_sizes, int n_in,
                              void* d_out, int out_size) {
    (void)in_sizes; (void)n_in; (void)out_size;
    const float* x = (const float*)d_in[0];
    float* out = (float*)d_out;
    init_consts_kernel<<<8, 128>>>();
    mfcc_kernel<<<NPAIR / GROUPS, THREADS>>>(x, out);
}

// round 17
// speedup vs baseline: 2.0742x; 1.0515x over previous
#include <cuda_runtime.h>
#include <math.h>

#define SR    16000
#define WIN   400
#define HOP   160
#define NFFT  512
#define NBIN  257
#define NMELS 40
#define NMFCC 13
#define BATCH 64
#define LEN   160000
#define NF    998
#define OUTC  39
#define NPAIR (BATCH * NF / 2)   // 31936 packed FFTs
#define GROUPS 4                 // FFT groups (64 thr each) per CTA
#define THREADS (GROUPS * 64)
#define NDCT  16                 // only mfcc[0..14] are ever needed
#define MAGSTRIDE 264            // compact magnitude layout stride (floats)
#define NTASK 80                 // 2 frames x 40 mel filters

// ================= compile-time table generation (no init kernel) =================
constexpr double CPI   = 3.141592653589793238462643383279502884;
constexpr double CLN10 = 2.302585092994045684017991454684364208;
constexpr double CLN2  = 0.693147180559945309417232121458176568;

constexpr double c_exp(double x) {           // |x| <= 3, Taylor
    double term = 1.0, sum = 1.0;
    for (int i = 1; i < 45; i++) { term *= x / (double)i; sum += term; }
    return sum;
}
constexpr double c_ln(double z) {            // z > 0
    int k = 0;
    while (z > 1.5)  { z *= 0.5; k++; }
    while (z < 0.75) { z *= 2.0; k--; }
    double t = (z - 1.0) / (z + 1.0);
    double t2 = t * t, term = t, sum = 0.0;
    for (int i = 0; i < 35; i++) { sum += term / (double)(2 * i + 1); term *= t2; }
    return 2.0 * sum + (double)k * CLN2;
}
constexpr double c_floor(double x) {
    long long i = (long long)x;
    return (double)i - (((double)i > x) ? 1.0 : 0.0);
}
constexpr double c_cos(double x) {           // x >= 0
    double tp = 2.0 * CPI;
    double k = c_floor(x / tp);
    double r = x - k * tp;                   // [0, 2pi)
    if (r > CPI) r = tp - r;                 // [0, pi]
    double r2 = r * r, term = 1.0, sum = 1.0;
    for (int i = 1; i < 28; i++) {
        term *= -r2 / (double)((2 * i - 1) * (2 * i));
        sum += term;
    }
    return sum;
}

struct Tables {
    float win[WIN];
    float fbw[NMELS * 33];   // packed sparse mel weights, stride 33 (zero-padded)
    int   klo[NMELS];
    int   flen[NMELS];
    float dct[NDCT * 41];    // first 16 DCT rows, stride 41 (zero-padded col 40)
    int   tmap[NTASK];       // load-balanced mel task permutation
};

constexpr Tables make_tables() {
    Tables T{};
    // mel bin edges (float64, floor) — exactly the numpy formula
    double bins[NMELS + 2] = {};
    double high_mel = 2595.0 * (c_ln(1.0 + ((double)SR / 2.0) / 700.0) / CLN10);
    for (int t = 0; t < NMELS + 2; t++) {
        double mel = high_mel * ((double)t / (double)(NMELS + 1));
        double hz = 700.0 * (c_exp(mel * (CLN10 / 2595.0)) - 1.0);   // 10^x = e^{x ln10}
        bins[t] = c_floor((double)(NFFT + 1) * hz / (double)SR);
    }
    // Hamming window (periodic)
    for (int n = 0; n < WIN; n++)
        T.win[n] = (float)(0.54 - 0.46 * c_cos(2.0 * CPI * (double)n / (double)WIN));
    // packed mel weights
    for (int r = 0; r < NMELS; r++) {
        int lo = (int)bins[r], c = (int)bins[r + 1], hi = (int)bins[r + 2];
        for (int j = 0; j < 33; j++) {
            int k = lo + j;
            double w = 0.0;
            if (k < c)       w = (double)(k - lo) / (double)(c - lo);
            else if (k < hi) w = (double)(hi - k) / (double)(hi - c);
            T.fbw[r * 33 + j] = (float)w;
        }
        T.klo[r] = lo;
        int len = hi - lo;
        T.flen[r] = len > 33 ? 33 : len;     // max actual width is 31
    }
    // DCT-II ortho, first 16 rows
    for (int i = 0; i < NDCT * 41; i++) {
        int k = i / 41, n = i % 41;
        double val = 0.0;
        if (n < NMELS) {
            double arg = CPI * (double)k * (2.0 * (double)n + 1.0) / 80.0;
            double sc = (k == 0) ? 0.15811388300841896660 : 0.22360679774997896964;
            val = sc * c_cos(arg);
        }
        T.dct[i] = (float)val;
    }
    // load-balanced mel task permutation (widths monotone in m -> analytic sort)
    for (int a = 0; a < NTASK; a++) {
        int m  = (NMELS - 1) - (a >> 1);
        int fr = a & 1;
        int slot = (a < 32) ? (32 + a) : ((a < 64) ? (a - 32) : a);
        T.tmap[slot] = fr * NMELS + m;
    }
    return T;
}

__device__ const Tables g_tab = make_tables();   // static (compile-time) init

// ---------------- complex helpers ----------------
__device__ __forceinline__ float2 cadd(float2 a, float2 b) { return make_float2(a.x + b.x, a.y + b.y); }
__device__ __forceinline__ float2 csub(float2 a, float2 b) { return make_float2(a.x - b.x, a.y - b.y); }
__device__ __forceinline__ float2 cmul(float2 a, float2 b) {
    return make_float2(a.x * b.x - a.y * b.y, a.x * b.y + a.y * b.x);
}
__device__ __forceinline__ float2 negi(float2 a) { return make_float2(a.y, -a.x); }  // -i*a

__device__ __forceinline__ void dft8(float2 v[8]) {
    const float c = 0.70710678118654752f;
    float2 t0 = cadd(v[0], v[4]), t1 = csub(v[0], v[4]);
    float2 t2 = cadd(v[2], v[6]), t3 = csub(v[2], v[6]);
    float2 E0 = cadd(t0, t2), E2 = csub(t0, t2);
    float2 t3n = negi(t3);
    float2 E1 = cadd(t1, t3n), E3 = csub(t1, t3n);
    float2 u0 = cadd(v[1], v[5]), u1 = csub(v[1], v[5]);
    float2 u2 = cadd(v[3], v[7]), u3 = csub(v[3], v[7]);
    float2 O0 = cadd(u0, u2), O2 = csub(u0, u2);
    float2 u3n = negi(u3);
    float2 O1 = cadd(u1, u3n), O3 = csub(u1, u3n);
    O1 = make_float2(c * (O1.x + O1.y), c * (O1.y - O1.x));
    O2 = negi(O2);
    O3 = make_float2(c * (O3.y - O3.x), -c * (O3.x + O3.y));
    v[0] = cadd(E0, O0); v[4] = csub(E0, O0);
    v[1] = cadd(E1, O1); v[5] = csub(E1, O1);
    v[2] = cadd(E2, O2); v[6] = csub(E2, O2);
    v[3] = cadd(E3, O3); v[7] = csub(E3, O3);
}

// apply twiddle powers w^1..w^7 with log-depth chain (depth 3 instead of 7)
__device__ __forceinline__ void twiddle_powers(float2 v[8], float2 w1) {
    float2 w2 = cmul(w1, w1);
    float2 w3 = cmul(w2, w1);
    float2 w4 = cmul(w2, w2);
    v[1] = cmul(v[1], w1);
    v[2] = cmul(v[2], w2);
    v[3] = cmul(v[3], w3);
    v[4] = cmul(v[4], w4);
    v[5] = cmul(v[5], cmul(w4, w1));
    v[6] = cmul(v[6], cmul(w4, w2));
    v[7] = cmul(v[7], cmul(w4, w3));
}

// ---------------- main kernel: one frame-pair per 64-thread group, 4 groups/CTA ----------------
__global__ __launch_bounds__(THREADS, 5) void mfcc_kernel(const float* __restrict__ x,
                                                          float* __restrict__ out) {
    __shared__ float2 sZ[GROUPS][568];            // FFT exchange buffer; mag overlay
    __shared__ float  sMel[GROUPS][2][NMELS];
    __shared__ float  sMfcc[GROUPS][2][NDCT];
    __shared__ float  sD1[GROUPS][2][NDCT];
    __shared__ float  sFbw[NMELS * 33];
    __shared__ int    sKlo[NMELS];
    __shared__ int    sLen[NMELS];
    __shared__ float  sDct[NDCT * 41];
    __shared__ int    sTask[NTASK];

    const int tid = threadIdx.x;
    const int lt  = tid & 63;
    const int grp = tid >> 6;
    const int p   = blockIdx.x * GROUPS + grp;    // packed-pair id (grid exact)
    const int b   = p / (NF / 2);
    const int fp  = p - b * (NF / 2);
    const int f0  = 2 * fp;
    const size_t row = (size_t)b * LEN;
    const int base0 = f0 * HOP;

    // cooperative table staging (coalesced), CTA-wide — amortized over 4 groups
    for (int i = tid; i < NMELS * 33; i += THREADS) sFbw[i] = g_tab.fbw[i];
    for (int i = tid; i < NDCT * 41;  i += THREADS) sDct[i] = g_tab.dct[i];
    if (tid < NMELS) { sKlo[tid] = g_tab.klo[tid]; sLen[tid] = g_tab.flen[tid]; }
    if (tid < NTASK) sTask[tid] = g_tab.tmap[tid];

    float2 v[8];

    // ---- load + pre-emphasis + window (direct dual LDG; coalesced & line-shared) ----
    #pragma unroll
    for (int j = 0; j < 8; j++) {
        int n = lt + 64 * j;
        if (n < WIN) {
            float w = g_tab.win[n];
            int i0 = base0 + n;
            float a0 = x[row + i0];
            float p0 = (i0 == 0) ? a0 : (a0 - 0.97f * x[row + i0 - 1]);
            int i1 = i0 + HOP;
            float a1 = x[row + i1];
            float p1 = a1 - 0.97f * x[row + i1 - 1];
            v[j] = make_float2(p0 * w, p1 * w);
        } else {
            v[j] = make_float2(0.0f, 0.0f);
        }
    }
    __syncthreads();   // tables staged + sZ free

    // ---- stage 1: radix-8 over stride 64, twiddle W512^(t*s) ----
    dft8(v);
    {
        float sv, cv;
        __sincosf(-0.01227184630308513f * (float)lt, &sv, &cv);   // -2*pi/512 * lt
        twiddle_powers(v, make_float2(cv, sv));
    }

    // exchange 1: store z_s[t] at 72*s + t ; read z_s[n'' + 8j']
    #pragma unroll
    for (int s = 0; s < 8; s++) sZ[grp][72 * s + lt] = v[s];
    __syncthreads();
    {
        const int s = lt >> 3, npp = lt & 7;
        #pragma unroll
        for (int j = 0; j < 8; j++) v[j] = sZ[grp][72 * s + npp + 8 * j];
        __syncthreads();

        // ---- stage 2: radix-8, twiddle W64^(n''*s') ----
        dft8(v);
        {
            float sv, cv;
            __sincosf(-0.0981747704246810f * (float)npp, &sv, &cv); // -2*pi/64 * npp
            twiddle_powers(v, make_float2(cv, sv));
        }

        // exchange 2: store at 68*n'' + 8*s' + s (bank-bijective per half-warp)
        #pragma unroll
        for (int sp = 0; sp < 8; sp++) sZ[grp][68 * npp + 8 * sp + s] = v[sp];
    }
    __syncthreads();
    {
        const int sp = lt >> 3, s = lt & 7;       // outputs X[64m + 8sp + s] = X[64m + lt]
        #pragma unroll
        for (int j = 0; j < 8; j++) v[j] = sZ[grp][68 * j + 8 * sp + s];
        __syncthreads();

        // ---- stage 3: radix-8 -> store X flat at slot 64*m + lt ----
        dft8(v);
        #pragma unroll
        for (int m = 0; m < 8; m++) sZ[grp][64 * m + lt] = v[m];
    }
    __syncthreads();

    // ---- conjugate-symmetry unpack into registers, then compact stride-1 store ----
    float m0[4], m1[4];
    #pragma unroll
    for (int j = 0; j < 4; j++) {
        int k  = lt + 64 * j;                     // 0..255
        int kk = (NFFT - k) & (NFFT - 1);
        float2 u = sZ[grp][k];
        float2 w = sZ[grp][kk];
        float Ar = 0.5f * (u.x + w.x), Ai = 0.5f * (u.y - w.y);
        float Br = 0.5f * (u.y + w.y), Bi = 0.5f * (w.x - u.x);
        m0[j] = sqrtf(Ar * Ar + Ai * Ai);
        m1[j] = sqrtf(Br * Br + Bi * Bi);
    }
    float e0 = 0.0f, e1 = 0.0f;
    if (lt == 0) {                                // k = 256 (Nyquist)
        float2 u = sZ[grp][256];
        e0 = fabsf(u.x); e1 = fabsf(u.y);
    }
    __syncthreads();                              // all spectrum reads done
    float* __restrict__ sMagF = (float*)sZ[grp];  // overlay: mag0 at [k], mag1 at [264+k]
    #pragma unroll
    for (int j = 0; j < 4; j++) {
        int k = lt + 64 * j;
        sMagF[k] = m0[j];
        sMagF[MAGSTRIDE + k] = m1[j];
    }
    if (lt == 0) { sMagF[256] = e0; sMagF[MAGSTRIDE + 256] = e1; }
    __syncthreads();

    // ---- mel filterbank + log: load-balanced task permutation ----
    #pragma unroll
    for (int sidx = lt; sidx < NTASK; sidx += 64) {
        int task = sTask[sidx];
        int fr = task / NMELS, m = task - fr * NMELS;
        const int klo = sKlo[m], len = sLen[m];
        const float* __restrict__ fw = sFbw + m * 33;
        const float* __restrict__ mg = sMagF + fr * MAGSTRIDE + klo;
        float acc = 0.0f;
        for (int j = 0; j < len; j++) acc = fmaf(fw[j], mg[j], acc);
        sMel[grp][fr][m] = __logf(acc + 1e-20f);
    }
    __syncthreads();

    // ---- DCT-II ortho, 16 rows, split dot across thread pairs ----
    {
        int task = lt >> 1;                       // 0..31 = (fr, m)
        int half = lt & 1;
        int fr = task >> 4, m = task & 15;
        const float* __restrict__ dr = sDct + m * 41 + half * 20;
        const float* __restrict__ ml = sMel[grp][fr] + half * 20;
        float acc = 0.0f;
        #pragma unroll
        for (int n = 0; n < 20; n++) acc = fmaf(dr[n], ml[n], acc);
        acc += __shfl_xor_sync(0xffffffffu, acc, 1);
        if (half == 0) sMfcc[grp][fr][m] = acc;
    }
    __syncthreads();

    // ---- first delta over coefficients (valid for c<=14; we need c<=13) ----
    if (lt < 32) {
        int fr = lt >> 4, c = lt & 15;
        float val = 0.0f;
        if (c >= 1 && c <= 14) val = 0.5f * (sMfcc[grp][fr][c + 1] - sMfcc[grp][fr][c - 1]);
        sD1[grp][fr][c] = val;
    }
    __syncthreads();

    // ---- write [mfcc[0:13], d1[0:13], d2[0:13]] for both frames ----
    #pragma unroll
    for (int i = lt; i < 2 * OUTC; i += 64) {
        int fr = i / OUTC, c = i - fr * OUTC;
        int frame = b * NF + f0 + fr;
        float val;
        if (c < NMFCC) {
            val = sMfcc[grp][fr][c];
        } else if (c < 2 * NMFCC) {
            val = sD1[grp][fr][c - NMFCC];
        } else {
            int cc = c - 2 * NMFCC;
            val = (cc >= 1) ? 0.5f * (sD1[grp][fr][cc + 1] - sD1[grp][fr][cc - 1]) : 0.0f;
        }
        out[(size_t)frame * OUTC + c] = val;
    }
}

extern "C" void kernel_launch(void* const* d_in, const int* in_sizes, int n_in,
                              void* d_out, int out_size) {
    (void)in_sizes; (void)n_in; (void)out_size;
    const float* x = (const float*)d_in[0];
    float* out = (float*)d_out;
    mfcc_kernel<<<NPAIR / GROUPS, THREADS>>>(x, out);
}